// round 11
// baseline (speedup 1.0000x reference)
#include <cuda_runtime.h>
#include <cuda_bf16.h>
#include <math.h>
#include <cstdint>

#define BB 2
#define SS 2048
#define DD 1024
#define HH 2816
#define EE 8
#define TT (BB*SS)

// ---------------- scratch (device globals; total ~386MB — proven safe) ------
__device__ float g_logits[TT*EE];
__device__ float g_probs [TT*EE];
__device__ float g_nrm   [BB*EE];
__device__ int   g_count [EE];
__device__ int   g_tok   [EE*TT];
__device__ float g_wt    [EE*TT];

__device__ __align__(256) __nv_bfloat16 d_xh[TT*DD], d_xl[TT*DD];     // 16.8MB
// H hi/lo interleaved: row (e*TT+r) -> hi at (row*2)*HH, lo at (row*2+1)*HH
__device__ __align__(256) __nv_bfloat16 d_h2[(size_t)EE*TT*2*HH];     // 369MB

// ---------------- PTX helpers ------------------------------------------------
__device__ __forceinline__ uint32_t smem_u32(const void* p) {
    uint32_t a;
    asm("{ .reg .u64 t; cvta.to.shared.u64 t, %1; cvt.u32.u64 %0, t; }"
        : "=r"(a) : "l"(p));
    return a;
}
#define SW64(o)  ((uint32_t)(o) ^ ((((uint32_t)(o)) >> 3) & 0x30))

__device__ __forceinline__ void cp16(uint32_t dst, const void* src) {
    asm volatile("cp.async.cg.shared.global [%0], [%1], 16;"
                 :: "r"(dst), "l"(__cvta_generic_to_global(src)) : "memory");
}
#define CP_COMMIT() asm volatile("cp.async.commit_group;" ::: "memory")
#define CP_WAIT0()  asm volatile("cp.async.wait_group 0;" ::: "memory")

__device__ __forceinline__ void ldsm4(uint32_t& r0, uint32_t& r1,
                                      uint32_t& r2, uint32_t& r3, uint32_t a) {
    asm volatile("ldmatrix.sync.aligned.m8n8.x4.shared.b16 {%0,%1,%2,%3}, [%4];"
                 : "=r"(r0), "=r"(r1), "=r"(r2), "=r"(r3) : "r"(a));
}
__device__ __forceinline__ void mma16816(float* c,
        uint32_t a0, uint32_t a1, uint32_t a2, uint32_t a3,
        uint32_t b0, uint32_t b1) {
    asm volatile("mma.sync.aligned.m16n8k16.row.col.f32.bf16.bf16.f32 "
        "{%0,%1,%2,%3},{%4,%5,%6,%7},{%8,%9},{%0,%1,%2,%3};"
        : "+f"(c[0]), "+f"(c[1]), "+f"(c[2]), "+f"(c[3])
        : "r"(a0), "r"(a1), "r"(a2), "r"(a3), "r"(b0), "r"(b1));
}

__device__ __forceinline__ void split1(float v, __nv_bfloat16& h, __nv_bfloat16& l) {
    h = __float2bfloat16(v);
    l = __float2bfloat16(v - __bfloat162float(h));
}

// Build one mma B reg pair (hi, lo) from fp32 staging.
// stage layout: [krow][n] with 256B rows (64 fp32). kr = absolute k row of the
// even element; n = absolute col. reg = bf16x2(elem k, elem k+1).
__device__ __forceinline__ void bfrag(const char* stage, int kr, int n,
                                      uint32_t& hi, uint32_t& lo) {
    float v0 = *(const float*)(stage + kr*256 + n*4);
    float v1 = *(const float*)(stage + kr*256 + 256 + n*4);
    __nv_bfloat16 h0,l0,h1,l1;
    split1(v0,h0,l0); split1(v1,h1,l1);
    __nv_bfloat162 H(h0,h1), L(l0,l1);
    hi = *(uint32_t*)&H;
    lo = *(uint32_t*)&L;
}

// ---------------- router + x-split fused (1st kernel) ------------------------
__global__ void router_k(const float* __restrict__ x,
                         const float* __restrict__ rw,
                         const float* __restrict__ rb) {
    int t = blockIdx.x;
    if (t == 0 && threadIdx.x < EE) g_count[threadIdx.x] = 0;

    {
        const float4* xr4 = (const float4*)(x + (size_t)t * DD);
        __nv_bfloat162* ph = (__nv_bfloat162*)(d_xh + (size_t)t * DD);
        __nv_bfloat162* pl = (__nv_bfloat162*)(d_xl + (size_t)t * DD);
#pragma unroll
        for (int i = 0; i < 2; i++) {
            int j = threadIdx.x + 128*i;
            float4 v = xr4[j];
            __nv_bfloat16 h0,l0,h1,l1,h2,l2,h3,l3;
            split1(v.x,h0,l0); split1(v.y,h1,l1);
            split1(v.z,h2,l2); split1(v.w,h3,l3);
            ph[j*2]   = __nv_bfloat162(h0,h1);  ph[j*2+1] = __nv_bfloat162(h2,h3);
            pl[j*2]   = __nv_bfloat162(l0,l1);  pl[j*2+1] = __nv_bfloat162(l2,l3);
        }
    }

    const float* xr = x + (size_t)t * DD;
    float acc[EE];
#pragma unroll
    for (int e = 0; e < EE; e++) acc[e] = 0.f;
    for (int d = threadIdx.x; d < DD; d += 128) {
        float xv = xr[d];
        const float4* r = (const float4*)(rw + (size_t)d * EE);
        float4 r0 = r[0], r1 = r[1];
        acc[0] += xv*r0.x; acc[1] += xv*r0.y; acc[2] += xv*r0.z; acc[3] += xv*r0.w;
        acc[4] += xv*r1.x; acc[5] += xv*r1.y; acc[6] += xv*r1.z; acc[7] += xv*r1.w;
    }
    __shared__ float sm[EE][128];
#pragma unroll
    for (int e = 0; e < EE; e++) sm[e][threadIdx.x] = acc[e];
    __syncthreads();
    for (int s = 64; s > 0; s >>= 1) {
        if (threadIdx.x < s)
#pragma unroll
            for (int e = 0; e < EE; e++) sm[e][threadIdx.x] += sm[e][threadIdx.x + s];
        __syncthreads();
    }
    if (threadIdx.x < EE)
        g_logits[(size_t)t*EE + threadIdx.x] = sm[threadIdx.x][0] + rb[threadIdx.x];
}

__global__ void norm_k() {
    int b = blockIdx.x >> 3, e = blockIdx.x & 7;
    float s = 0.f;
    for (int i = threadIdx.x; i < SS; i += 256) {
        float v = g_logits[((size_t)(b*SS + i))*EE + e];
        s += v*v;
    }
    __shared__ float sm[256];
    sm[threadIdx.x] = s; __syncthreads();
    for (int st = 128; st > 0; st >>= 1) {
        if (threadIdx.x < st) sm[threadIdx.x] += sm[threadIdx.x + st];
        __syncthreads();
    }
    if (threadIdx.x == 0) g_nrm[blockIdx.x] = fmaxf(sqrtf(sm[0]), 1e-12f);
}

__global__ void route_k() {
    int t = blockIdx.x*blockDim.x + threadIdx.x;
    if (t >= TT) return;
    int b = t / SS;
    float l[EE]; float m = -1e30f;
#pragma unroll
    for (int e = 0; e < EE; e++) {
        l[e] = g_logits[(size_t)t*EE + e] / g_nrm[b*EE + e];
        m = fmaxf(m, l[e]);
    }
    float sum = 0.f;
#pragma unroll
    for (int e = 0; e < EE; e++) { l[e] = expf(l[e]-m); sum += l[e]; }
    float inv = 1.f/sum;
#pragma unroll
    for (int e = 0; e < EE; e++) { l[e] *= inv; g_probs[(size_t)t*EE + e] = l[e]; }
    int i0 = 0;
#pragma unroll
    for (int e = 1; e < EE; e++) if (l[e] > l[i0]) i0 = e;
    int i1 = -1;
#pragma unroll
    for (int e = 0; e < EE; e++) {
        if (e == i0) continue;
        if (i1 < 0 || l[e] > l[i1]) i1 = e;
    }
    int s0 = atomicAdd(&g_count[i0], 1);
    g_tok[i0*TT + s0] = t; g_wt[i0*TT + s0] = l[i0];
    int s1 = atomicAdd(&g_count[i1], 1);
    g_tok[i1*TT + s1] = t; g_wt[i1*TT + s1] = l[i1];
}

__global__ void aux_k(float* __restrict__ out_aux) {
    float acc = 0.f;
    for (int i = threadIdx.x; i < SS*EE; i += 256) {
        int s = i >> 3, e = i & 7;
        float a = 0.5f*(g_probs[(size_t)s*EE + e] + g_probs[(size_t)(SS+s)*EE + e]);
        float d = 0.125f - a;
        acc += d*d;
    }
    __shared__ float sm[256];
    sm[threadIdx.x] = acc; __syncthreads();
    for (int st = 128; st > 0; st >>= 1) {
        if (threadIdx.x < st) sm[threadIdx.x] += sm[threadIdx.x + st];
        __syncthreads();
    }
    if (threadIdx.x == 0) out_aux[0] = sm[0];
}

// ---------------- GEMM1 (HMMA, direct-LDS B frags, 2 CTAs/SM) ----------------
// M=128, N=64 per matrix; K-stage=32.
// smem: AB(p)=p*16384 (XH 8K + XL 8K, SW64 bf16)
//       ST(q)=32768+q*16384 (fp32 B: w1 8K + w3 8K, [krow][n] 256B rows)
//       stok @ 65536
#define G1_AB(p)  ((p)*16384)
#define G1_ST(q)  (32768 + (q)*16384)
#define G1_SMEM   66048
#define G1_NS     (DD/32)

__global__ __launch_bounds__(256, 2)
void gemm1_k(const float* __restrict__ w1, const float* __restrict__ w3) {
    extern __shared__ char smem[];
    int e = blockIdx.z;
    int cnt = g_count[e];
    int row0 = blockIdx.y * 128;
    if (row0 >= cnt) return;
    int col0 = blockIdx.x * 64;

    int tid = threadIdx.x, wid = tid >> 5, lane = tid & 31;
    uint32_t sb = smem_u32(smem);
    int* stok = (int*)(smem + 65536);

    if (tid < 128) stok[tid] = g_tok[e*TT + min(row0 + tid, cnt-1)];
    __syncthreads();

    int warpM = (wid & 1) * 64;
    int warpN = (wid >> 1) * 16;
    int fr  = (lane & 7) + ((lane >> 3) & 1) * 8;
    int fkb = (lane >> 4) * 16;
    int klane = 2*(lane & 3);     // even k row within k16 block
    int nlane = lane >> 2;        // col within 8-col group

    auto cpA = [&](int s) {
        int kk = s*32;
        uint32_t base = sb + G1_AB(s & 1);
#pragma unroll
        for (int i = 0; i < 4; i++) {
            int g = tid + 256*i;
            int buf = g >> 9, idx = g & 511;
            int row = idx >> 2, c = idx & 3;
            const __nv_bfloat16* src =
                (buf ? d_xl : d_xh) + (size_t)stok[row]*DD + kk + c*8;
            cp16(base + buf*8192 + SW64(row*64 + c*16), src);
        }
    };
    auto cpB32 = [&](int s) {
        int kk = s*32;
        uint32_t base = sb + G1_ST(s & 1);
#pragma unroll
        for (int i = 0; i < 4; i++) {
            int g = tid + 256*i;
            int mat = g >> 9, idx = g & 511;
            int krow = idx >> 4, nch = idx & 15;
            const float* wp = mat ? w3 : w1;
            cp16(base + mat*8192 + krow*256 + nch*16,
                 wp + ((size_t)(e*DD + kk + krow))*HH + col0 + nch*4);
        }
    };

    float c1[4][2][4], c3[4][2][4];
#pragma unroll
    for (int i = 0; i < 4; i++)
#pragma unroll
        for (int j = 0; j < 2; j++)
#pragma unroll
            for (int r = 0; r < 4; r++) { c1[i][j][r] = 0.f; c3[i][j][r] = 0.f; }

    cpA(0); cpB32(0); CP_COMMIT();
    CP_WAIT0(); __syncthreads();

    for (int s = 0; s < G1_NS; s++) {
        int p = s & 1;
        if (s + 1 < G1_NS) { cpA(s + 1); cpB32(s + 1); }
        CP_COMMIT();

        uint32_t ab = sb + G1_AB(p);
        const char* st1 = smem + G1_ST(p);
        const char* st3 = st1 + 8192;
#pragma unroll
        for (int k16 = 0; k16 < 2; k16++) {
            // B fragments built straight from fp32 staging (conflict-free LDS)
            uint32_t b1h[4], b1l[4], b3h[4], b3l[4];
#pragma unroll
            for (int nt = 0; nt < 2; nt++)
#pragma unroll
                for (int kh = 0; kh < 2; kh++) {
                    int kr = k16*16 + kh*8 + klane;
                    int nn = warpN + nt*8 + nlane;
                    bfrag(st1, kr, nn, b1h[nt*2+kh], b1l[nt*2+kh]);
                    bfrag(st3, kr, nn, b3h[nt*2+kh], b3l[nt*2+kh]);
                }
            // per-mt: A loads immediately followed by their 12 MMAs
#pragma unroll
            for (int mt = 0; mt < 4; mt++) {
                uint32_t offA = SW64((warpM + mt*16 + fr)*64 + k16*32 + fkb);
                uint32_t ah[4], al[4];
                ldsm4(ah[0], ah[1], ah[2], ah[3], ab + offA);
                ldsm4(al[0], al[1], al[2], al[3], ab + 8192 + offA);
#pragma unroll
                for (int nt = 0; nt < 2; nt++) {
                    mma16816(c1[mt][nt], ah[0],ah[1],ah[2],ah[3], b1h[nt*2], b1h[nt*2+1]);
                    mma16816(c3[mt][nt], ah[0],ah[1],ah[2],ah[3], b3h[nt*2], b3h[nt*2+1]);
                    mma16816(c1[mt][nt], al[0],al[1],al[2],al[3], b1h[nt*2], b1h[nt*2+1]);
                    mma16816(c3[mt][nt], al[0],al[1],al[2],al[3], b3h[nt*2], b3h[nt*2+1]);
                    mma16816(c1[mt][nt], ah[0],ah[1],ah[2],ah[3], b1l[nt*2], b1l[nt*2+1]);
                    mma16816(c3[mt][nt], ah[0],ah[1],ah[2],ah[3], b3l[nt*2], b3l[nt*2+1]);
                }
            }
        }

        if (s + 1 < G1_NS) { CP_WAIT0(); __syncthreads(); }
    }

    // epilogue
#pragma unroll
    for (int mt = 0; mt < 4; mt++) {
#pragma unroll
        for (int half = 0; half < 2; half++) {
            int rg = row0 + warpM + mt*16 + (lane >> 2) + half*8;
            if (rg < cnt) {
                size_t rowi = (size_t)(e*TT + rg);
                size_t cb = col0 + warpN + (lane & 3)*2;
#pragma unroll
                for (int nt = 0; nt < 2; nt++) {
                    float s0 = c1[mt][nt][half*2],   g0 = c3[mt][nt][half*2];
                    float s1 = c1[mt][nt][half*2+1], g1 = c3[mt][nt][half*2+1];
                    float v0 = __sinf(s0)*g0, v1 = __sinf(s1)*g1;
                    __nv_bfloat16 h0,l0,h1,l1;
                    split1(v0,h0,l0); split1(v1,h1,l1);
                    *(__nv_bfloat162*)(d_h2 + (rowi*2)*HH   + cb + nt*8) = __nv_bfloat162(h0,h1);
                    *(__nv_bfloat162*)(d_h2 + (rowi*2+1)*HH + cb + nt*8) = __nv_bfloat162(l0,l1);
                }
            }
        }
    }
}

// ---------------- GEMM2 (HMMA, direct-LDS B frags, 2 CTAs/SM) ----------------
// smem: AB(p)=p*16384 (AH+AL) | ST(q)=32768+q*8192 (fp32 w2, 256B rows)
//       ctrl @ 49152
#define G2_AB(p)  ((p)*16384)
#define G2_ST(q)  (32768 + (q)*8192)
#define G2_SMEM   50176
#define G2_NS     (HH/32)

__global__ __launch_bounds__(256, 2)
void gemm2_k(const float* __restrict__ w2, float* __restrict__ out) {
    extern __shared__ char smem[];
    int e = blockIdx.z;
    int cnt = g_count[e];
    int row0 = blockIdx.y * 128;
    if (row0 >= cnt) return;
    int col0 = blockIdx.x * 64;

    int tid = threadIdx.x, wid = tid >> 5, lane = tid & 31;
    uint32_t sb = smem_u32(smem);
    int*   stok = (int*)(smem + 49152);
    float* swt  = (float*)(smem + 49152 + 512);

    if (tid < 128) {
        int r = min(row0 + tid, cnt-1);
        stok[tid] = g_tok[e*TT + r];
        swt[tid]  = g_wt[e*TT + r];
    }
    __syncthreads();

    int warpM = (wid & 1) * 64;
    int warpN = (wid >> 1) * 16;
    int fr  = (lane & 7) + ((lane >> 3) & 1) * 8;
    int fkb = (lane >> 4) * 16;
    int klane = 2*(lane & 3);
    int nlane = lane >> 2;
    size_t arow0 = (size_t)(e*TT + row0);

    auto cpA = [&](int s) {
        int kk = s*32;
        uint32_t base = sb + G2_AB(s & 1);
#pragma unroll
        for (int i = 0; i < 4; i++) {
            int g = tid + 256*i;
            int buf = g >> 9, idx = g & 511;
            int row = idx >> 2, c = idx & 3;
            const __nv_bfloat16* src =
                d_h2 + ((arow0 + row)*2 + buf)*HH + kk + c*8;
            cp16(base + buf*8192 + SW64(row*64 + c*16), src);
        }
    };
    auto cpB32 = [&](int s) {
        int kk = s*32;
        uint32_t base = sb + G2_ST(s & 1);
#pragma unroll
        for (int i = 0; i < 2; i++) {
            int g = tid + 256*i;
            int krow = g >> 4, nch = g & 15;
            cp16(base + krow*256 + nch*16,
                 w2 + ((size_t)(e*HH + kk + krow))*DD + col0 + nch*4);
        }
    };

    float cc[4][2][4];
#pragma unroll
    for (int i = 0; i < 4; i++)
#pragma unroll
        for (int j = 0; j < 2; j++)
#pragma unroll
            for (int r = 0; r < 4; r++) cc[i][j][r] = 0.f;

    cpA(0); cpB32(0); CP_COMMIT();
    CP_WAIT0(); __syncthreads();

    for (int s = 0; s < G2_NS; s++) {
        int p = s & 1;
        if (s + 1 < G2_NS) { cpA(s + 1); cpB32(s + 1); }
        CP_COMMIT();

        uint32_t ab = sb + G2_AB(p);
        const char* stw = smem + G2_ST(p);
#pragma unroll
        for (int k16 = 0; k16 < 2; k16++) {
            uint32_t bh[4], bl[4];
#pragma unroll
            for (int nt = 0; nt < 2; nt++)
#pragma unroll
                for (int kh = 0; kh < 2; kh++) {
                    int kr = k16*16 + kh*8 + klane;
                    int nn = warpN + nt*8 + nlane;
                    bfrag(stw, kr, nn, bh[nt*2+kh], bl[nt*2+kh]);
                }
#pragma unroll
            for (int mt = 0; mt < 4; mt++) {
                uint32_t offA = SW64((warpM + mt*16 + fr)*64 + k16*32 + fkb);
                uint32_t ah[4], al[4];
                ldsm4(ah[0], ah[1], ah[2], ah[3], ab + offA);
                ldsm4(al[0], al[1], al[2], al[3], ab + 8192 + offA);
#pragma unroll
                for (int nt = 0; nt < 2; nt++) {
                    mma16816(cc[mt][nt], ah[0],ah[1],ah[2],ah[3], bh[nt*2], bh[nt*2+1]);
                    mma16816(cc[mt][nt], al[0],al[1],al[2],al[3], bh[nt*2], bh[nt*2+1]);
                    mma16816(cc[mt][nt], ah[0],ah[1],ah[2],ah[3], bl[nt*2], bl[nt*2+1]);
                }
            }
        }

        if (s + 1 < G2_NS) { CP_WAIT0(); __syncthreads(); }
    }

    // epilogue: weighted atomic scatter
#pragma unroll
    for (int mt = 0; mt < 4; mt++) {
#pragma unroll
        for (int half = 0; half < 2; half++) {
            int ml = warpM + mt*16 + (lane >> 2) + half*8;
            if (row0 + ml < cnt) {
                int   tok = stok[ml];
                float wt  = swt[ml];
                float* op = out + (size_t)tok*DD + col0 + warpN + (lane & 3)*2;
#pragma unroll
                for (int nt = 0; nt < 2; nt++) {
                    atomicAdd(op + nt*8 + 0, wt * cc[mt][nt][half*2]);
                    atomicAdd(op + nt*8 + 1, wt * cc[mt][nt][half*2+1]);
                }
            }
        }
    }
}

// ---------------- launch -----------------------------------------------------
extern "C" void kernel_launch(void* const* d_in, const int* in_sizes, int n_in,
                              void* d_out, int out_size) {
    const float* x  = (const float*)d_in[0];
    const float* w1 = (const float*)d_in[1];
    const float* w2 = (const float*)d_in[2];
    const float* w3 = (const float*)d_in[3];
    const float* rw = (const float*)d_in[4];
    const float* rb = (const float*)d_in[5];
    float* out = (float*)d_out;

    cudaFuncSetAttribute(gemm1_k, cudaFuncAttributeMaxDynamicSharedMemorySize, G1_SMEM);
    cudaFuncSetAttribute(gemm2_k, cudaFuncAttributeMaxDynamicSharedMemorySize, G2_SMEM);

    cudaMemsetAsync(d_out, 0, (size_t)out_size * sizeof(float));

    router_k<<<TT, 128>>>(x, rw, rb);                       // kernel 1 (+split+init)
    norm_k<<<BB*EE, 256>>>();                               // kernel 2
    route_k<<<TT/256, 256>>>();                             // kernel 3
    gemm1_k<<<dim3(HH/64, TT/128, EE), 256, G1_SMEM>>>(w1, w3);   // kernel 4 (ncu)
    gemm2_k<<<dim3(DD/64, TT/128, EE), 256, G2_SMEM>>>(w2, out);  // kernel 5
    if (out_size > TT*DD) aux_k<<<1, 256>>>(out + (size_t)TT*DD); // kernel 6
}

// round 13
// speedup vs baseline: 1.1047x; 1.1047x over previous
#include <cuda_runtime.h>
#include <cuda_bf16.h>
#include <math.h>
#include <cstdint>

#define BB 2
#define SS 2048
#define DD 1024
#define HH 2816
#define EE 8
#define TT (BB*SS)

// ---------------- scratch (device globals; total ~386MB — proven safe) ------
__device__ float g_logits[TT*EE];
__device__ float g_probs [TT*EE];
__device__ float g_nrm   [BB*EE];
__device__ int   g_count [EE];
__device__ int   g_tok   [EE*TT];
__device__ float g_wt    [EE*TT];

__device__ __align__(256) __nv_bfloat16 d_xh[TT*DD], d_xl[TT*DD];     // 16.8MB
// H hi/lo interleaved: row (e*TT+r) -> hi at (row*2)*HH, lo at (row*2+1)*HH
__device__ __align__(256) __nv_bfloat16 d_h2[(size_t)EE*TT*2*HH];     // 369MB

// ---------------- PTX helpers ------------------------------------------------
__device__ __forceinline__ uint32_t smem_u32(const void* p) {
    uint32_t a;
    asm("{ .reg .u64 t; cvta.to.shared.u64 t, %1; cvt.u32.u64 %0, t; }"
        : "=r"(a) : "l"(p));
    return a;
}
#define SW64(o)  ((uint32_t)(o) ^ ((((uint32_t)(o)) >> 3) & 0x30))
#define SW128(o) ((uint32_t)(o) ^ ((((uint32_t)(o)) >> 3) & 0x70))

__device__ __forceinline__ void cp16(uint32_t dst, const void* src) {
    asm volatile("cp.async.cg.shared.global [%0], [%1], 16;"
                 :: "r"(dst), "l"(__cvta_generic_to_global(src)) : "memory");
}
#define CP_COMMIT() asm volatile("cp.async.commit_group;" ::: "memory")
#define CP_WAIT0()  asm volatile("cp.async.wait_group 0;" ::: "memory")

__device__ __forceinline__ void ldsm4(uint32_t& r0, uint32_t& r1,
                                      uint32_t& r2, uint32_t& r3, uint32_t a) {
    asm volatile("ldmatrix.sync.aligned.m8n8.x4.shared.b16 {%0,%1,%2,%3}, [%4];"
                 : "=r"(r0), "=r"(r1), "=r"(r2), "=r"(r3) : "r"(a));
}
__device__ __forceinline__ void ldsm4t(uint32_t& r0, uint32_t& r1,
                                       uint32_t& r2, uint32_t& r3, uint32_t a) {
    asm volatile("ldmatrix.sync.aligned.m8n8.x4.trans.shared.b16 {%0,%1,%2,%3}, [%4];"
                 : "=r"(r0), "=r"(r1), "=r"(r2), "=r"(r3) : "r"(a));
}
__device__ __forceinline__ void mma16816(float* c,
        uint32_t a0, uint32_t a1, uint32_t a2, uint32_t a3,
        uint32_t b0, uint32_t b1) {
    asm volatile("mma.sync.aligned.m16n8k16.row.col.f32.bf16.bf16.f32 "
        "{%0,%1,%2,%3},{%4,%5,%6,%7},{%8,%9},{%0,%1,%2,%3};"
        : "+f"(c[0]), "+f"(c[1]), "+f"(c[2]), "+f"(c[3])
        : "r"(a0), "r"(a1), "r"(a2), "r"(a3), "r"(b0), "r"(b1));
}

__device__ __forceinline__ void split1(float v, __nv_bfloat16& h, __nv_bfloat16& l) {
    h = __float2bfloat16(v);
    l = __float2bfloat16(v - __bfloat162float(h));
}

union BP4 { unsigned long long u; __nv_bfloat16 h[4]; };

// ---------------- router + x-split fused (1st kernel) ------------------------
__global__ void router_k(const float* __restrict__ x,
                         const float* __restrict__ rw,
                         const float* __restrict__ rb) {
    int t = blockIdx.x;
    if (t == 0 && threadIdx.x < EE) g_count[threadIdx.x] = 0;

    {
        const float4* xr4 = (const float4*)(x + (size_t)t * DD);
        __nv_bfloat162* ph = (__nv_bfloat162*)(d_xh + (size_t)t * DD);
        __nv_bfloat162* pl = (__nv_bfloat162*)(d_xl + (size_t)t * DD);
#pragma unroll
        for (int i = 0; i < 2; i++) {
            int j = threadIdx.x + 128*i;
            float4 v = xr4[j];
            __nv_bfloat16 h0,l0,h1,l1,h2,l2,h3,l3;
            split1(v.x,h0,l0); split1(v.y,h1,l1);
            split1(v.z,h2,l2); split1(v.w,h3,l3);
            ph[j*2]   = __nv_bfloat162(h0,h1);  ph[j*2+1] = __nv_bfloat162(h2,h3);
            pl[j*2]   = __nv_bfloat162(l0,l1);  pl[j*2+1] = __nv_bfloat162(l2,l3);
        }
    }

    const float* xr = x + (size_t)t * DD;
    float acc[EE];
#pragma unroll
    for (int e = 0; e < EE; e++) acc[e] = 0.f;
    for (int d = threadIdx.x; d < DD; d += 128) {
        float xv = xr[d];
        const float4* r = (const float4*)(rw + (size_t)d * EE);
        float4 r0 = r[0], r1 = r[1];
        acc[0] += xv*r0.x; acc[1] += xv*r0.y; acc[2] += xv*r0.z; acc[3] += xv*r0.w;
        acc[4] += xv*r1.x; acc[5] += xv*r1.y; acc[6] += xv*r1.z; acc[7] += xv*r1.w;
    }
    __shared__ float sm[EE][128];
#pragma unroll
    for (int e = 0; e < EE; e++) sm[e][threadIdx.x] = acc[e];
    __syncthreads();
    for (int s = 64; s > 0; s >>= 1) {
        if (threadIdx.x < s)
#pragma unroll
            for (int e = 0; e < EE; e++) sm[e][threadIdx.x] += sm[e][threadIdx.x + s];
        __syncthreads();
    }
    if (threadIdx.x < EE)
        g_logits[(size_t)t*EE + threadIdx.x] = sm[threadIdx.x][0] + rb[threadIdx.x];
}

__global__ void norm_k() {
    int b = blockIdx.x >> 3, e = blockIdx.x & 7;
    float s = 0.f;
    for (int i = threadIdx.x; i < SS; i += 256) {
        float v = g_logits[((size_t)(b*SS + i))*EE + e];
        s += v*v;
    }
    __shared__ float sm[256];
    sm[threadIdx.x] = s; __syncthreads();
    for (int st = 128; st > 0; st >>= 1) {
        if (threadIdx.x < st) sm[threadIdx.x] += sm[threadIdx.x + st];
        __syncthreads();
    }
    if (threadIdx.x == 0) g_nrm[blockIdx.x] = fmaxf(sqrtf(sm[0]), 1e-12f);
}

__global__ void route_k() {
    int t = blockIdx.x*blockDim.x + threadIdx.x;
    if (t >= TT) return;
    int b = t / SS;
    float l[EE]; float m = -1e30f;
#pragma unroll
    for (int e = 0; e < EE; e++) {
        l[e] = g_logits[(size_t)t*EE + e] / g_nrm[b*EE + e];
        m = fmaxf(m, l[e]);
    }
    float sum = 0.f;
#pragma unroll
    for (int e = 0; e < EE; e++) { l[e] = expf(l[e]-m); sum += l[e]; }
    float inv = 1.f/sum;
#pragma unroll
    for (int e = 0; e < EE; e++) { l[e] *= inv; g_probs[(size_t)t*EE + e] = l[e]; }
    int i0 = 0;
#pragma unroll
    for (int e = 1; e < EE; e++) if (l[e] > l[i0]) i0 = e;
    int i1 = -1;
#pragma unroll
    for (int e = 0; e < EE; e++) {
        if (e == i0) continue;
        if (i1 < 0 || l[e] > l[i1]) i1 = e;
    }
    int s0 = atomicAdd(&g_count[i0], 1);
    g_tok[i0*TT + s0] = t; g_wt[i0*TT + s0] = l[i0];
    int s1 = atomicAdd(&g_count[i1], 1);
    g_tok[i1*TT + s1] = t; g_wt[i1*TT + s1] = l[i1];
}

__global__ void aux_k(float* __restrict__ out_aux) {
    float acc = 0.f;
    for (int i = threadIdx.x; i < SS*EE; i += 256) {
        int s = i >> 3, e = i & 7;
        float a = 0.5f*(g_probs[(size_t)s*EE + e] + g_probs[(size_t)(SS+s)*EE + e]);
        float d = 0.125f - a;
        acc += d*d;
    }
    __shared__ float sm[256];
    sm[threadIdx.x] = acc; __syncthreads();
    for (int st = 128; st > 0; st >>= 1) {
        if (threadIdx.x < st) sm[threadIdx.x] += sm[threadIdx.x + st];
        __syncthreads();
    }
    if (threadIdx.x == 0) out_aux[0] = sm[0];
}

// ---------------- GEMM1 (R10 best: HMMA, 1-sync pipelined, 2 CTAs/SM) --------
#define G1_AB(p)  ((p)*16384)
#define G1_BB(p)  (32768 + (p)*16384)
#define G1_ST(q)  (65536 + (q)*16384)
#define G1_SMEM   98816
#define G1_NS     (DD/32)

__global__ __launch_bounds__(256, 2)
void gemm1_k(const float* __restrict__ w1, const float* __restrict__ w3) {
    extern __shared__ char smem[];
    int e = blockIdx.z;
    int cnt = g_count[e];
    int row0 = blockIdx.y * 128;
    if (row0 >= cnt) return;
    int col0 = blockIdx.x * 64;

    int tid = threadIdx.x, wid = tid >> 5, lane = tid & 31;
    uint32_t sb = smem_u32(smem);
    int* stok = (int*)(smem + 98304);

    if (tid < 128) stok[tid] = g_tok[e*TT + min(row0 + tid, cnt-1)];
    __syncthreads();

    int warpM = (wid & 1) * 64;
    int warpN = (wid >> 1) * 16;
    int fr  = (lane & 7) + ((lane >> 3) & 1) * 8;
    int fkb = (lane >> 4) * 16;

    auto cpA = [&](int s) {
        int kk = s*32;
        uint32_t base = sb + G1_AB(s & 1);
#pragma unroll
        for (int i = 0; i < 4; i++) {
            int g = tid + 256*i;
            int buf = g >> 9, idx = g & 511;
            int row = idx >> 2, c = idx & 3;
            const __nv_bfloat16* src =
                (buf ? d_xl : d_xh) + (size_t)stok[row]*DD + kk + c*8;
            cp16(base + buf*8192 + SW64(row*64 + c*16), src);
        }
    };
    auto cpB32 = [&](int s) {
        int kk = s*32;
        uint32_t base = sb + G1_ST(s & 1);
#pragma unroll
        for (int i = 0; i < 4; i++) {
            int g = tid + 256*i;
            int mat = g >> 9, idx = g & 511;
            int krow = idx >> 4, nch = idx & 15;
            const float* wp = mat ? w3 : w1;
            cp16(base + mat*8192 + krow*256 + nch*16,
                 wp + ((size_t)(e*DD + kk + krow))*HH + col0 + nch*4);
        }
    };
    auto convB = [&](int j) {
        char* src = smem + G1_ST(j & 1);
        char* dst = smem + G1_BB(j & 1);
#pragma unroll
        for (int i = 0; i < 4; i++) {
            int g = tid + 256*i;
            int mat = g >> 9, idx = g & 511;
            int krow = idx >> 4, nch = idx & 15;
            float4 v = *(float4*)(src + mat*8192 + krow*256 + nch*16);
            BP4 ph, pl;
            split1(v.x, ph.h[0], pl.h[0]);
            split1(v.y, ph.h[1], pl.h[1]);
            split1(v.z, ph.h[2], pl.h[2]);
            split1(v.w, ph.h[3], pl.h[3]);
            uint32_t off = SW128(krow*128 + nch*8);
            *(unsigned long long*)(dst + mat*8192 + off)        = ph.u;
            *(unsigned long long*)(dst + mat*8192 + 4096 + off) = pl.u;
        }
    };

    float c1[4][2][4], c3[4][2][4];
#pragma unroll
    for (int i = 0; i < 4; i++)
#pragma unroll
        for (int j = 0; j < 2; j++)
#pragma unroll
            for (int r = 0; r < 4; r++) { c1[i][j][r] = 0.f; c3[i][j][r] = 0.f; }

    cpA(0); cpB32(0); cpB32(1); CP_COMMIT();
    CP_WAIT0(); __syncthreads();
    convB(0);
    __syncthreads();

    for (int s = 0; s < G1_NS; s++) {
        int p = s & 1;
        if (s + 1 < G1_NS) cpA(s + 1);
        if (s + 2 < G1_NS) cpB32(s + 2);
        CP_COMMIT();
        if (s + 1 < G1_NS) convB(s + 1);   // overlaps with MMA below

        uint32_t ab = sb + G1_AB(p), bb = sb + G1_BB(p);
#pragma unroll
        for (int k16 = 0; k16 < 2; k16++) {
            uint32_t offB = SW128((k16*16 + fr)*128 + warpN*2 + fkb);
            uint32_t b1h[4], b1l[4], b3h[4], b3l[4];
            ldsm4t(b1h[0], b1h[1], b1h[2], b1h[3], bb + offB);
            ldsm4t(b1l[0], b1l[1], b1l[2], b1l[3], bb + 4096 + offB);
            ldsm4t(b3h[0], b3h[1], b3h[2], b3h[3], bb + 8192 + offB);
            ldsm4t(b3l[0], b3l[1], b3l[2], b3l[3], bb + 12288 + offB);
#pragma unroll
            for (int mt = 0; mt < 4; mt++) {
                uint32_t offA = SW64((warpM + mt*16 + fr)*64 + k16*32 + fkb);
                uint32_t ah[4], al[4];
                ldsm4(ah[0], ah[1], ah[2], ah[3], ab + offA);
                ldsm4(al[0], al[1], al[2], al[3], ab + 8192 + offA);
#pragma unroll
                for (int nt = 0; nt < 2; nt++) {
                    mma16816(c1[mt][nt], ah[0],ah[1],ah[2],ah[3], b1h[nt*2], b1h[nt*2+1]);
                    mma16816(c3[mt][nt], ah[0],ah[1],ah[2],ah[3], b3h[nt*2], b3h[nt*2+1]);
                    mma16816(c1[mt][nt], al[0],al[1],al[2],al[3], b1h[nt*2], b1h[nt*2+1]);
                    mma16816(c3[mt][nt], al[0],al[1],al[2],al[3], b3h[nt*2], b3h[nt*2+1]);
                    mma16816(c1[mt][nt], ah[0],ah[1],ah[2],ah[3], b1l[nt*2], b1l[nt*2+1]);
                    mma16816(c3[mt][nt], ah[0],ah[1],ah[2],ah[3], b3l[nt*2], b3l[nt*2+1]);
                }
            }
        }

        if (s + 1 < G1_NS) { CP_WAIT0(); __syncthreads(); }
    }

    // epilogue
#pragma unroll
    for (int mt = 0; mt < 4; mt++) {
#pragma unroll
        for (int half = 0; half < 2; half++) {
            int rg = row0 + warpM + mt*16 + (lane >> 2) + half*8;
            if (rg < cnt) {
                size_t rowi = (size_t)(e*TT + rg);
                size_t cb = col0 + warpN + (lane & 3)*2;
#pragma unroll
                for (int nt = 0; nt < 2; nt++) {
                    float s0 = c1[mt][nt][half*2],   g0 = c3[mt][nt][half*2];
                    float s1 = c1[mt][nt][half*2+1], g1 = c3[mt][nt][half*2+1];
                    float v0 = __sinf(s0)*g0, v1 = __sinf(s1)*g1;
                    __nv_bfloat16 h0,l0,h1,l1;
                    split1(v0,h0,l0); split1(v1,h1,l1);
                    *(__nv_bfloat162*)(d_h2 + (rowi*2)*HH   + cb + nt*8) = __nv_bfloat162(h0,h1);
                    *(__nv_bfloat162*)(d_h2 + (rowi*2+1)*HH + cb + nt*8) = __nv_bfloat162(l0,l1);
                }
            }
        }
    }
}

// ---------------- GEMM2 (HMMA, N=128 CTA tile, warp M64xN32, 2 CTAs/SM) ------
#define G2_AB(p)  ((p)*16384)
#define G2_BB(p)  (32768 + (p)*16384)
#define G2_ST(q)  (65536 + (q)*16384)
#define G2_SMEM   99328
#define G2_NS     (HH/32)

__global__ __launch_bounds__(256, 2)
void gemm2_k(const float* __restrict__ w2, float* __restrict__ out) {
    extern __shared__ char smem[];
    int e = blockIdx.z;
    int cnt = g_count[e];
    int row0 = blockIdx.y * 128;
    if (row0 >= cnt) return;
    int col0 = blockIdx.x * 128;

    int tid = threadIdx.x, wid = tid >> 5, lane = tid & 31;
    uint32_t sb = smem_u32(smem);
    int*   stok = (int*)(smem + 98304);
    float* swt  = (float*)(smem + 98304 + 512);

    if (tid < 128) {
        int r = min(row0 + tid, cnt-1);
        stok[tid] = g_tok[e*TT + r];
        swt[tid]  = g_wt[e*TT + r];
    }
    __syncthreads();

    int warpM = (wid & 1) * 64;
    int warpN = (wid >> 1) * 32;            // 0,32,64,96
    int nhalf = warpN >> 6;                  // column half (0/1)
    int nloc  = warpN & 63;                  // col within half (0 or 32)
    int fr  = (lane & 7) + ((lane >> 3) & 1) * 8;
    int fkb = (lane >> 4) * 16;
    size_t arow0 = (size_t)(e*TT + row0);

    auto cpA = [&](int s) {
        int kk = s*32;
        uint32_t base = sb + G2_AB(s & 1);
#pragma unroll
        for (int i = 0; i < 4; i++) {
            int g = tid + 256*i;
            int buf = g >> 9, idx = g & 511;
            int row = idx >> 2, c = idx & 3;
            const __nv_bfloat16* src =
                d_h2 + ((arow0 + row)*2 + buf)*HH + kk + c*8;
            cp16(base + buf*8192 + SW64(row*64 + c*16), src);
        }
    };
    auto cpB32 = [&](int s) {
        int kk = s*32;
        uint32_t base = sb + G2_ST(s & 1);
#pragma unroll
        for (int i = 0; i < 4; i++) {
            int g = tid + 256*i;            // 1024 chunks: 32 krows x 32 nch
            int krow = g >> 5, nch = g & 31;
            cp16(base + krow*512 + nch*16,
                 w2 + ((size_t)(e*HH + kk + krow))*DD + col0 + nch*4);
        }
    };
    auto convB = [&](int j) {
        char* src = smem + G2_ST(j & 1);
        char* dst = smem + G2_BB(j & 1);
#pragma unroll
        for (int i = 0; i < 4; i++) {
            int g = tid + 256*i;
            int krow = g >> 5, nch = g & 31;
            float4 v = *(float4*)(src + krow*512 + nch*16);
            BP4 ph, pl;
            split1(v.x, ph.h[0], pl.h[0]);
            split1(v.y, ph.h[1], pl.h[1]);
            split1(v.z, ph.h[2], pl.h[2]);
            split1(v.w, ph.h[3], pl.h[3]);
            int half = nch >> 4, colc = nch & 15;
            uint32_t off = SW128(krow*128 + colc*8);
            *(unsigned long long*)(dst + half*8192 + off)        = ph.u;
            *(unsigned long long*)(dst + half*8192 + 4096 + off) = pl.u;
        }
    };

    float cc[4][4][4];
#pragma unroll
    for (int i = 0; i < 4; i++)
#pragma unroll
        for (int j = 0; j < 4; j++)
#pragma unroll
            for (int r = 0; r < 4; r++) cc[i][j][r] = 0.f;

    cpA(0); cpB32(0); cpB32(1); CP_COMMIT();
    CP_WAIT0(); __syncthreads();
    convB(0);
    __syncthreads();

    for (int s = 0; s < G2_NS; s++) {
        int p = s & 1;
        if (s + 1 < G2_NS) cpA(s + 1);
        if (s + 2 < G2_NS) cpB32(s + 2);
        CP_COMMIT();
        if (s + 1 < G2_NS) convB(s + 1);

        uint32_t ab = sb + G2_AB(p);
        uint32_t bbh = sb + G2_BB(p) + nhalf*8192;
#pragma unroll
        for (int k16 = 0; k16 < 2; k16++) {
            uint32_t offB0 = SW128((k16*16 + fr)*128 + nloc*2 + fkb);
            uint32_t offB1 = SW128((k16*16 + fr)*128 + (nloc+16)*2 + fkb);
            uint32_t bhA[4], bhB[4], blA[4], blB[4];
            ldsm4t(bhA[0], bhA[1], bhA[2], bhA[3], bbh + offB0);
            ldsm4t(bhB[0], bhB[1], bhB[2], bhB[3], bbh + offB1);
            ldsm4t(blA[0], blA[1], blA[2], blA[3], bbh + 4096 + offB0);
            ldsm4t(blB[0], blB[1], blB[2], blB[3], bbh + 4096 + offB1);
#pragma unroll
            for (int mt = 0; mt < 4; mt++) {
                uint32_t offA = SW64((warpM + mt*16 + fr)*64 + k16*32 + fkb);
                uint32_t ah[4], al[4];
                ldsm4(ah[0], ah[1], ah[2], ah[3], ab + offA);
                ldsm4(al[0], al[1], al[2], al[3], ab + 8192 + offA);
#pragma unroll
                for (int nt = 0; nt < 2; nt++) {
                    // first 16 cols (frag set A): pairs (r0,r1)/(r2,r3)
                    mma16816(cc[mt][nt], ah[0],ah[1],ah[2],ah[3], bhA[nt*2], bhA[nt*2+1]);
                    mma16816(cc[mt][nt], al[0],al[1],al[2],al[3], bhA[nt*2], bhA[nt*2+1]);
                    mma16816(cc[mt][nt], ah[0],ah[1],ah[2],ah[3], blA[nt*2], blA[nt*2+1]);
                    // second 16 cols (frag set B)
                    mma16816(cc[mt][nt+2], ah[0],ah[1],ah[2],ah[3], bhB[nt*2], bhB[nt*2+1]);
                    mma16816(cc[mt][nt+2], al[0],al[1],al[2],al[3], bhB[nt*2], bhB[nt*2+1]);
                    mma16816(cc[mt][nt+2], ah[0],ah[1],ah[2],ah[3], blB[nt*2], blB[nt*2+1]);
                }
            }
        }

        if (s + 1 < G2_NS) { CP_WAIT0(); __syncthreads(); }
    }

    // epilogue: weighted atomic scatter (nt 0,1 -> cols +0,+8; nt 2,3 -> +16,+24)
#pragma unroll
    for (int mt = 0; mt < 4; mt++) {
#pragma unroll
        for (int half = 0; half < 2; half++) {
            int ml = warpM + mt*16 + (lane >> 2) + half*8;
            if (row0 + ml < cnt) {
                int   tok = stok[ml];
                float wt  = swt[ml];
                float* op = out + (size_t)tok*DD + col0 + warpN + (lane & 3)*2;
#pragma unroll
                for (int nt = 0; nt < 4; nt++) {
                    atomicAdd(op + nt*8 + 0, wt * cc[mt][nt][half*2]);
                    atomicAdd(op + nt*8 + 1, wt * cc[mt][nt][half*2+1]);
                }
            }
        }
    }
}

// ---------------- launch -----------------------------------------------------
extern "C" void kernel_launch(void* const* d_in, const int* in_sizes, int n_in,
                              void* d_out, int out_size) {
    const float* x  = (const float*)d_in[0];
    const float* w1 = (const float*)d_in[1];
    const float* w2 = (const float*)d_in[2];
    const float* w3 = (const float*)d_in[3];
    const float* rw = (const float*)d_in[4];
    const float* rb = (const float*)d_in[5];
    float* out = (float*)d_out;

    cudaFuncSetAttribute(gemm1_k, cudaFuncAttributeMaxDynamicSharedMemorySize, G1_SMEM);
    cudaFuncSetAttribute(gemm2_k, cudaFuncAttributeMaxDynamicSharedMemorySize, G2_SMEM);

    cudaMemsetAsync(d_out, 0, (size_t)out_size * sizeof(float));

    router_k<<<TT, 128>>>(x, rw, rb);                       // kernel 1 (+split+init)
    norm_k<<<BB*EE, 256>>>();                               // kernel 2
    route_k<<<TT/256, 256>>>();                             // kernel 3
    gemm1_k<<<dim3(HH/64, TT/128, EE), 256, G1_SMEM>>>(w1, w3);   // kernel 4 (ncu)
    gemm2_k<<<dim3(DD/128, TT/128, EE), 256, G2_SMEM>>>(w2, out); // kernel 5
    if (out_size > TT*DD) aux_k<<<1, 256>>>(out + (size_t)TT*DD); // kernel 6
}

// round 14
// speedup vs baseline: 1.1114x; 1.0060x over previous
#include <cuda_runtime.h>
#include <cuda_bf16.h>
#include <math.h>
#include <cstdint>

#define BB 2
#define SS 2048
#define DD 1024
#define HH 2816
#define EE 8
#define TT (BB*SS)

// ---------------- scratch (device globals; total ~386MB — proven safe) ------
__device__ float g_logits[TT*EE];
__device__ float g_probs [TT*EE];
__device__ float g_nrm   [BB*EE];
__device__ int   g_count [EE];
__device__ int   g_tok   [EE*TT];
__device__ float g_wt    [EE*TT];

__device__ __align__(256) __nv_bfloat16 d_xh[TT*DD], d_xl[TT*DD];     // 16.8MB
__device__ __align__(256) __nv_bfloat16 d_h2[(size_t)EE*TT*2*HH];     // 369MB

// ---------------- PTX helpers ------------------------------------------------
__device__ __forceinline__ uint32_t smem_u32(const void* p) {
    uint32_t a;
    asm("{ .reg .u64 t; cvta.to.shared.u64 t, %1; cvt.u32.u64 %0, t; }"
        : "=r"(a) : "l"(p));
    return a;
}
#define SW64(o)  ((uint32_t)(o) ^ ((((uint32_t)(o)) >> 3) & 0x30))
#define SW128(o) ((uint32_t)(o) ^ ((((uint32_t)(o)) >> 3) & 0x70))

__device__ __forceinline__ void cp16(uint32_t dst, const void* src) {
    asm volatile("cp.async.cg.shared.global [%0], [%1], 16;"
                 :: "r"(dst), "l"(__cvta_generic_to_global(src)) : "memory");
}
#define CP_COMMIT() asm volatile("cp.async.commit_group;" ::: "memory")
#define CP_WAIT(n)  asm volatile("cp.async.wait_group %0;" :: "n"(n) : "memory")

__device__ __forceinline__ void ldsm4(uint32_t& r0, uint32_t& r1,
                                      uint32_t& r2, uint32_t& r3, uint32_t a) {
    asm volatile("ldmatrix.sync.aligned.m8n8.x4.shared.b16 {%0,%1,%2,%3}, [%4];"
                 : "=r"(r0), "=r"(r1), "=r"(r2), "=r"(r3) : "r"(a));
}
__device__ __forceinline__ void ldsm4t(uint32_t& r0, uint32_t& r1,
                                       uint32_t& r2, uint32_t& r3, uint32_t a) {
    asm volatile("ldmatrix.sync.aligned.m8n8.x4.trans.shared.b16 {%0,%1,%2,%3}, [%4];"
                 : "=r"(r0), "=r"(r1), "=r"(r2), "=r"(r3) : "r"(a));
}
__device__ __forceinline__ void mma16816(float* c,
        uint32_t a0, uint32_t a1, uint32_t a2, uint32_t a3,
        uint32_t b0, uint32_t b1) {
    asm volatile("mma.sync.aligned.m16n8k16.row.col.f32.bf16.bf16.f32 "
        "{%0,%1,%2,%3},{%4,%5,%6,%7},{%8,%9},{%0,%1,%2,%3};"
        : "+f"(c[0]), "+f"(c[1]), "+f"(c[2]), "+f"(c[3])
        : "r"(a0), "r"(a1), "r"(a2), "r"(a3), "r"(b0), "r"(b1));
}

__device__ __forceinline__ void split1(float v, __nv_bfloat16& h, __nv_bfloat16& l) {
    h = __float2bfloat16(v);
    l = __float2bfloat16(v - __bfloat162float(h));
}

union BP4 { unsigned long long u; __nv_bfloat16 h[4]; };

// ---------------- router + x-split fused (1st kernel) ------------------------
__global__ void router_k(const float* __restrict__ x,
                         const float* __restrict__ rw,
                         const float* __restrict__ rb) {
    int t = blockIdx.x;
    if (t == 0 && threadIdx.x < EE) g_count[threadIdx.x] = 0;

    {
        const float4* xr4 = (const float4*)(x + (size_t)t * DD);
        __nv_bfloat162* ph = (__nv_bfloat162*)(d_xh + (size_t)t * DD);
        __nv_bfloat162* pl = (__nv_bfloat162*)(d_xl + (size_t)t * DD);
#pragma unroll
        for (int i = 0; i < 2; i++) {
            int j = threadIdx.x + 128*i;
            float4 v = xr4[j];
            __nv_bfloat16 h0,l0,h1,l1,h2,l2,h3,l3;
            split1(v.x,h0,l0); split1(v.y,h1,l1);
            split1(v.z,h2,l2); split1(v.w,h3,l3);
            ph[j*2]   = __nv_bfloat162(h0,h1);  ph[j*2+1] = __nv_bfloat162(h2,h3);
            pl[j*2]   = __nv_bfloat162(l0,l1);  pl[j*2+1] = __nv_bfloat162(l2,l3);
        }
    }

    const float* xr = x + (size_t)t * DD;
    float acc[EE];
#pragma unroll
    for (int e = 0; e < EE; e++) acc[e] = 0.f;
    for (int d = threadIdx.x; d < DD; d += 128) {
        float xv = xr[d];
        const float4* r = (const float4*)(rw + (size_t)d * EE);
        float4 r0 = r[0], r1 = r[1];
        acc[0] += xv*r0.x; acc[1] += xv*r0.y; acc[2] += xv*r0.z; acc[3] += xv*r0.w;
        acc[4] += xv*r1.x; acc[5] += xv*r1.y; acc[6] += xv*r1.z; acc[7] += xv*r1.w;
    }
    __shared__ float sm[EE][128];
#pragma unroll
    for (int e = 0; e < EE; e++) sm[e][threadIdx.x] = acc[e];
    __syncthreads();
    for (int s = 64; s > 0; s >>= 1) {
        if (threadIdx.x < s)
#pragma unroll
            for (int e = 0; e < EE; e++) sm[e][threadIdx.x] += sm[e][threadIdx.x + s];
        __syncthreads();
    }
    if (threadIdx.x < EE)
        g_logits[(size_t)t*EE + threadIdx.x] = sm[threadIdx.x][0] + rb[threadIdx.x];
}

__global__ void norm_k() {
    int b = blockIdx.x >> 3, e = blockIdx.x & 7;
    float s = 0.f;
    for (int i = threadIdx.x; i < SS; i += 256) {
        float v = g_logits[((size_t)(b*SS + i))*EE + e];
        s += v*v;
    }
    __shared__ float sm[256];
    sm[threadIdx.x] = s; __syncthreads();
    for (int st = 128; st > 0; st >>= 1) {
        if (threadIdx.x < st) sm[threadIdx.x] += sm[threadIdx.x + st];
        __syncthreads();
    }
    if (threadIdx.x == 0) g_nrm[blockIdx.x] = fmaxf(sqrtf(sm[0]), 1e-12f);
}

__global__ void route_k() {
    int t = blockIdx.x*blockDim.x + threadIdx.x;
    if (t >= TT) return;
    int b = t / SS;
    float l[EE]; float m = -1e30f;
#pragma unroll
    for (int e = 0; e < EE; e++) {
        l[e] = g_logits[(size_t)t*EE + e] / g_nrm[b*EE + e];
        m = fmaxf(m, l[e]);
    }
    float sum = 0.f;
#pragma unroll
    for (int e = 0; e < EE; e++) { l[e] = expf(l[e]-m); sum += l[e]; }
    float inv = 1.f/sum;
#pragma unroll
    for (int e = 0; e < EE; e++) { l[e] *= inv; g_probs[(size_t)t*EE + e] = l[e]; }
    int i0 = 0;
#pragma unroll
    for (int e = 1; e < EE; e++) if (l[e] > l[i0]) i0 = e;
    int i1 = -1;
#pragma unroll
    for (int e = 0; e < EE; e++) {
        if (e == i0) continue;
        if (i1 < 0 || l[e] > l[i1]) i1 = e;
    }
    int s0 = atomicAdd(&g_count[i0], 1);
    g_tok[i0*TT + s0] = t; g_wt[i0*TT + s0] = l[i0];
    int s1 = atomicAdd(&g_count[i1], 1);
    g_tok[i1*TT + s1] = t; g_wt[i1*TT + s1] = l[i1];
}

__global__ void aux_k(float* __restrict__ out_aux) {
    float acc = 0.f;
    for (int i = threadIdx.x; i < SS*EE; i += 256) {
        int s = i >> 3, e = i & 7;
        float a = 0.5f*(g_probs[(size_t)s*EE + e] + g_probs[(size_t)(SS+s)*EE + e]);
        float d = 0.125f - a;
        acc += d*d;
    }
    __shared__ float sm[256];
    sm[threadIdx.x] = acc; __syncthreads();
    for (int st = 128; st > 0; st >>= 1) {
        if (threadIdx.x < st) sm[threadIdx.x] += sm[threadIdx.x + st];
        __syncthreads();
    }
    if (threadIdx.x == 0) out_aux[0] = sm[0];
}

// ---------------- GEMM1 (HMMA, split-group pipelined, 2 CTAs/SM) -------------
#define G1_AB(p)  ((p)*16384)
#define G1_BB(p)  (32768 + (p)*16384)
#define G1_ST(q)  (65536 + (q)*16384)
#define G1_SMEM   98816
#define G1_NS     (DD/32)

__global__ __launch_bounds__(256, 2)
void gemm1_k(const float* __restrict__ w1, const float* __restrict__ w3) {
    extern __shared__ char smem[];
    int e = blockIdx.z;
    int cnt = g_count[e];
    int row0 = blockIdx.y * 128;
    if (row0 >= cnt) return;
    int col0 = blockIdx.x * 64;

    int tid = threadIdx.x, wid = tid >> 5, lane = tid & 31;
    uint32_t sb = smem_u32(smem);
    int* stok = (int*)(smem + 98304);

    if (tid < 128) stok[tid] = g_tok[e*TT + min(row0 + tid, cnt-1)];
    __syncthreads();

    int warpM = (wid & 1) * 64;
    int warpN = (wid >> 1) * 16;
    int fr  = (lane & 7) + ((lane >> 3) & 1) * 8;
    int fkb = (lane >> 4) * 16;

    auto cpA = [&](int s) {
        int kk = s*32;
        uint32_t base = sb + G1_AB(s & 1);
#pragma unroll
        for (int i = 0; i < 4; i++) {
            int g = tid + 256*i;
            int buf = g >> 9, idx = g & 511;
            int row = idx >> 2, c = idx & 3;
            const __nv_bfloat16* src =
                (buf ? d_xl : d_xh) + (size_t)stok[row]*DD + kk + c*8;
            cp16(base + buf*8192 + SW64(row*64 + c*16), src);
        }
    };
    auto cpB32 = [&](int s) {
        int kk = s*32;
        uint32_t base = sb + G1_ST(s & 1);
#pragma unroll
        for (int i = 0; i < 4; i++) {
            int g = tid + 256*i;
            int mat = g >> 9, idx = g & 511;
            int krow = idx >> 4, nch = idx & 15;
            const float* wp = mat ? w3 : w1;
            cp16(base + mat*8192 + krow*256 + nch*16,
                 wp + ((size_t)(e*DD + kk + krow))*HH + col0 + nch*4);
        }
    };
    auto convB = [&](int j) {
        char* src = smem + G1_ST(j & 1);
        char* dst = smem + G1_BB(j & 1);
#pragma unroll
        for (int i = 0; i < 4; i++) {
            int g = tid + 256*i;
            int mat = g >> 9, idx = g & 511;
            int krow = idx >> 4, nch = idx & 15;
            float4 v = *(float4*)(src + mat*8192 + krow*256 + nch*16);
            BP4 ph, pl;
            split1(v.x, ph.h[0], pl.h[0]);
            split1(v.y, ph.h[1], pl.h[1]);
            split1(v.z, ph.h[2], pl.h[2]);
            split1(v.w, ph.h[3], pl.h[3]);
            uint32_t off = SW128(krow*128 + nch*8);
            *(unsigned long long*)(dst + mat*8192 + off)        = ph.u;
            *(unsigned long long*)(dst + mat*8192 + 4096 + off) = pl.u;
        }
    };

    float c1[4][2][4], c3[4][2][4];
#pragma unroll
    for (int i = 0; i < 4; i++)
#pragma unroll
        for (int j = 0; j < 2; j++)
#pragma unroll
            for (int r = 0; r < 4; r++) { c1[i][j][r] = 0.f; c3[i][j][r] = 0.f; }

    // prologue: A0 | B0 | B1 as separate groups
    cpA(0);   CP_COMMIT();
    cpB32(0); CP_COMMIT();
    cpB32(1); CP_COMMIT();
    CP_WAIT(1);              // A0, B0 done; B1 may fly
    convB(0);
    __syncthreads();

    for (int s = 0; s < G1_NS; s++) {
        int p = s & 1;
        if (s + 1 < G1_NS) cpA(s + 1);
        CP_COMMIT();                       // group A(s+1)
        if (s + 2 < G1_NS) cpB32(s + 2);
        CP_COMMIT();                       // group B(s+2)

        uint32_t ab = sb + G1_AB(p), bb = sb + G1_BB(p);
#pragma unroll
        for (int k16 = 0; k16 < 2; k16++) {
            uint32_t offB = SW128((k16*16 + fr)*128 + warpN*2 + fkb);
            uint32_t b1h[4], b1l[4], b3h[4], b3l[4];
            ldsm4t(b1h[0], b1h[1], b1h[2], b1h[3], bb + offB);
            ldsm4t(b1l[0], b1l[1], b1l[2], b1l[3], bb + 4096 + offB);
            ldsm4t(b3h[0], b3h[1], b3h[2], b3h[3], bb + 8192 + offB);
            ldsm4t(b3l[0], b3l[1], b3l[2], b3l[3], bb + 12288 + offB);
#pragma unroll
            for (int mt = 0; mt < 4; mt++) {
                uint32_t offA = SW64((warpM + mt*16 + fr)*64 + k16*32 + fkb);
                uint32_t ah[4], al[4];
                ldsm4(ah[0], ah[1], ah[2], ah[3], ab + offA);
                ldsm4(al[0], al[1], al[2], al[3], ab + 8192 + offA);
#pragma unroll
                for (int nt = 0; nt < 2; nt++) {
                    mma16816(c1[mt][nt], ah[0],ah[1],ah[2],ah[3], b1h[nt*2], b1h[nt*2+1]);
                    mma16816(c3[mt][nt], ah[0],ah[1],ah[2],ah[3], b3h[nt*2], b3h[nt*2+1]);
                    mma16816(c1[mt][nt], al[0],al[1],al[2],al[3], b1h[nt*2], b1h[nt*2+1]);
                    mma16816(c3[mt][nt], al[0],al[1],al[2],al[3], b3h[nt*2], b3h[nt*2+1]);
                    mma16816(c1[mt][nt], ah[0],ah[1],ah[2],ah[3], b1l[nt*2], b1l[nt*2+1]);
                    mma16816(c3[mt][nt], ah[0],ah[1],ah[2],ah[3], b3l[nt*2], b3l[nt*2+1]);
                }
            }
        }

        if (s + 1 < G1_NS) {
            CP_WAIT(2);          // B(s+1) complete (A(s+1), B(s+2) may fly)
            convB(s + 1);        // overlaps the remaining A wait
            CP_WAIT(1);          // A(s+1) complete
            __syncthreads();
        }
    }

    // epilogue
#pragma unroll
    for (int mt = 0; mt < 4; mt++) {
#pragma unroll
        for (int half = 0; half < 2; half++) {
            int rg = row0 + warpM + mt*16 + (lane >> 2) + half*8;
            if (rg < cnt) {
                size_t rowi = (size_t)(e*TT + rg);
                size_t cb = col0 + warpN + (lane & 3)*2;
#pragma unroll
                for (int nt = 0; nt < 2; nt++) {
                    float s0 = c1[mt][nt][half*2],   g0 = c3[mt][nt][half*2];
                    float s1 = c1[mt][nt][half*2+1], g1 = c3[mt][nt][half*2+1];
                    float v0 = __sinf(s0)*g0, v1 = __sinf(s1)*g1;
                    __nv_bfloat16 h0,l0,h1,l1;
                    split1(v0,h0,l0); split1(v1,h1,l1);
                    *(__nv_bfloat162*)(d_h2 + (rowi*2)*HH   + cb + nt*8) = __nv_bfloat162(h0,h1);
                    *(__nv_bfloat162*)(d_h2 + (rowi*2+1)*HH + cb + nt*8) = __nv_bfloat162(l0,l1);
                }
            }
        }
    }
}

// ---------------- GEMM2 (HMMA, N=128, split-group pipelined, 2 CTAs/SM) ------
#define G2_AB(p)  ((p)*16384)
#define G2_BB(p)  (32768 + (p)*16384)
#define G2_ST(q)  (65536 + (q)*16384)
#define G2_SMEM   99328
#define G2_NS     (HH/32)

__global__ __launch_bounds__(256, 2)
void gemm2_k(const float* __restrict__ w2, float* __restrict__ out) {
    extern __shared__ char smem[];
    int e = blockIdx.z;
    int cnt = g_count[e];
    int row0 = blockIdx.y * 128;
    if (row0 >= cnt) return;
    int col0 = blockIdx.x * 128;

    int tid = threadIdx.x, wid = tid >> 5, lane = tid & 31;
    uint32_t sb = smem_u32(smem);
    int*   stok = (int*)(smem + 98304);
    float* swt  = (float*)(smem + 98304 + 512);

    if (tid < 128) {
        int r = min(row0 + tid, cnt-1);
        stok[tid] = g_tok[e*TT + r];
        swt[tid]  = g_wt[e*TT + r];
    }
    __syncthreads();

    int warpM = (wid & 1) * 64;
    int warpN = (wid >> 1) * 32;
    int nhalf = warpN >> 6;
    int nloc  = warpN & 63;
    int fr  = (lane & 7) + ((lane >> 3) & 1) * 8;
    int fkb = (lane >> 4) * 16;
    size_t arow0 = (size_t)(e*TT + row0);

    auto cpA = [&](int s) {
        int kk = s*32;
        uint32_t base = sb + G2_AB(s & 1);
#pragma unroll
        for (int i = 0; i < 4; i++) {
            int g = tid + 256*i;
            int buf = g >> 9, idx = g & 511;
            int row = idx >> 2, c = idx & 3;
            const __nv_bfloat16* src =
                d_h2 + ((arow0 + row)*2 + buf)*HH + kk + c*8;
            cp16(base + buf*8192 + SW64(row*64 + c*16), src);
        }
    };
    auto cpB32 = [&](int s) {
        int kk = s*32;
        uint32_t base = sb + G2_ST(s & 1);
#pragma unroll
        for (int i = 0; i < 4; i++) {
            int g = tid + 256*i;
            int krow = g >> 5, nch = g & 31;
            cp16(base + krow*512 + nch*16,
                 w2 + ((size_t)(e*HH + kk + krow))*DD + col0 + nch*4);
        }
    };
    auto convB = [&](int j) {
        char* src = smem + G2_ST(j & 1);
        char* dst = smem + G2_BB(j & 1);
#pragma unroll
        for (int i = 0; i < 4; i++) {
            int g = tid + 256*i;
            int krow = g >> 5, nch = g & 31;
            float4 v = *(float4*)(src + krow*512 + nch*16);
            BP4 ph, pl;
            split1(v.x, ph.h[0], pl.h[0]);
            split1(v.y, ph.h[1], pl.h[1]);
            split1(v.z, ph.h[2], pl.h[2]);
            split1(v.w, ph.h[3], pl.h[3]);
            int half = nch >> 4, colc = nch & 15;
            uint32_t off = SW128(krow*128 + colc*8);
            *(unsigned long long*)(dst + half*8192 + off)        = ph.u;
            *(unsigned long long*)(dst + half*8192 + 4096 + off) = pl.u;
        }
    };

    float cc[4][4][4];
#pragma unroll
    for (int i = 0; i < 4; i++)
#pragma unroll
        for (int j = 0; j < 4; j++)
#pragma unroll
            for (int r = 0; r < 4; r++) cc[i][j][r] = 0.f;

    cpA(0);   CP_COMMIT();
    cpB32(0); CP_COMMIT();
    cpB32(1); CP_COMMIT();
    CP_WAIT(1);
    convB(0);
    __syncthreads();

    for (int s = 0; s < G2_NS; s++) {
        int p = s & 1;
        if (s + 1 < G2_NS) cpA(s + 1);
        CP_COMMIT();
        if (s + 2 < G2_NS) cpB32(s + 2);
        CP_COMMIT();

        uint32_t ab = sb + G2_AB(p);
        uint32_t bbh = sb + G2_BB(p) + nhalf*8192;
#pragma unroll
        for (int k16 = 0; k16 < 2; k16++) {
            uint32_t offB0 = SW128((k16*16 + fr)*128 + nloc*2 + fkb);
            uint32_t offB1 = SW128((k16*16 + fr)*128 + (nloc+16)*2 + fkb);
            uint32_t bhA[4], bhB[4], blA[4], blB[4];
            ldsm4t(bhA[0], bhA[1], bhA[2], bhA[3], bbh + offB0);
            ldsm4t(bhB[0], bhB[1], bhB[2], bhB[3], bbh + offB1);
            ldsm4t(blA[0], blA[1], blA[2], blA[3], bbh + 4096 + offB0);
            ldsm4t(blB[0], blB[1], blB[2], blB[3], bbh + 4096 + offB1);
#pragma unroll
            for (int mt = 0; mt < 4; mt++) {
                uint32_t offA = SW64((warpM + mt*16 + fr)*64 + k16*32 + fkb);
                uint32_t ah[4], al[4];
                ldsm4(ah[0], ah[1], ah[2], ah[3], ab + offA);
                ldsm4(al[0], al[1], al[2], al[3], ab + 8192 + offA);
#pragma unroll
                for (int nt = 0; nt < 2; nt++) {
                    mma16816(cc[mt][nt], ah[0],ah[1],ah[2],ah[3], bhA[nt*2], bhA[nt*2+1]);
                    mma16816(cc[mt][nt], al[0],al[1],al[2],al[3], bhA[nt*2], bhA[nt*2+1]);
                    mma16816(cc[mt][nt], ah[0],ah[1],ah[2],ah[3], blA[nt*2], blA[nt*2+1]);
                    mma16816(cc[mt][nt+2], ah[0],ah[1],ah[2],ah[3], bhB[nt*2], bhB[nt*2+1]);
                    mma16816(cc[mt][nt+2], al[0],al[1],al[2],al[3], bhB[nt*2], bhB[nt*2+1]);
                    mma16816(cc[mt][nt+2], ah[0],ah[1],ah[2],ah[3], blB[nt*2], blB[nt*2+1]);
                }
            }
        }

        if (s + 1 < G2_NS) {
            CP_WAIT(2);
            convB(s + 1);
            CP_WAIT(1);
            __syncthreads();
        }
    }

    // epilogue: weighted atomic scatter
#pragma unroll
    for (int mt = 0; mt < 4; mt++) {
#pragma unroll
        for (int half = 0; half < 2; half++) {
            int ml = warpM + mt*16 + (lane >> 2) + half*8;
            if (row0 + ml < cnt) {
                int   tok = stok[ml];
                float wt  = swt[ml];
                float* op = out + (size_t)tok*DD + col0 + warpN + (lane & 3)*2;
#pragma unroll
                for (int nt = 0; nt < 4; nt++) {
                    atomicAdd(op + nt*8 + 0, wt * cc[mt][nt][half*2]);
                    atomicAdd(op + nt*8 + 1, wt * cc[mt][nt][half*2+1]);
                }
            }
        }
    }
}

// ---------------- launch -----------------------------------------------------
extern "C" void kernel_launch(void* const* d_in, const int* in_sizes, int n_in,
                              void* d_out, int out_size) {
    const float* x  = (const float*)d_in[0];
    const float* w1 = (const float*)d_in[1];
    const float* w2 = (const float*)d_in[2];
    const float* w3 = (const float*)d_in[3];
    const float* rw = (const float*)d_in[4];
    const float* rb = (const float*)d_in[5];
    float* out = (float*)d_out;

    cudaFuncSetAttribute(gemm1_k, cudaFuncAttributeMaxDynamicSharedMemorySize, G1_SMEM);
    cudaFuncSetAttribute(gemm2_k, cudaFuncAttributeMaxDynamicSharedMemorySize, G2_SMEM);

    cudaMemsetAsync(d_out, 0, (size_t)out_size * sizeof(float));

    router_k<<<TT, 128>>>(x, rw, rb);                       // kernel 1 (+split+init)
    norm_k<<<BB*EE, 256>>>();                               // kernel 2
    route_k<<<TT/256, 256>>>();                             // kernel 3
    gemm1_k<<<dim3(HH/64, TT/128, EE), 256, G1_SMEM>>>(w1, w3);   // kernel 4 (ncu)
    gemm2_k<<<dim3(DD/128, TT/128, EE), 256, G2_SMEM>>>(w2, out); // kernel 5
    if (out_size > TT*DD) aux_k<<<1, 256>>>(out + (size_t)TT*DD); // kernel 6
}

// round 15
// speedup vs baseline: 1.1285x; 1.0154x over previous
#include <cuda_runtime.h>
#include <cuda_bf16.h>
#include <math.h>
#include <cstdint>

#define BB 2
#define SS 2048
#define DD 1024
#define HH 2816
#define EE 8
#define TT (BB*SS)

// ---------------- scratch (device globals; total ~386MB — proven safe) ------
__device__ float g_logits[TT*EE];
__device__ float g_probs [TT*EE];
__device__ float g_nrm   [BB*EE];
__device__ int   g_count [EE];
__device__ int   g_tok   [EE*TT];
__device__ float g_wt    [EE*TT];

__device__ __align__(256) __nv_bfloat16 d_xh[TT*DD], d_xl[TT*DD];     // 16.8MB
__device__ __align__(256) __nv_bfloat16 d_h2[(size_t)EE*TT*2*HH];     // 369MB

// ---------------- PTX helpers ------------------------------------------------
__device__ __forceinline__ uint32_t smem_u32(const void* p) {
    uint32_t a;
    asm("{ .reg .u64 t; cvta.to.shared.u64 t, %1; cvt.u32.u64 %0, t; }"
        : "=r"(a) : "l"(p));
    return a;
}
#define SW64(o)  ((uint32_t)(o) ^ ((((uint32_t)(o)) >> 3) & 0x30))
#define SW128(o) ((uint32_t)(o) ^ ((((uint32_t)(o)) >> 3) & 0x70))

__device__ __forceinline__ void cp16(uint32_t dst, const void* src) {
    asm volatile("cp.async.cg.shared.global [%0], [%1], 16;"
                 :: "r"(dst), "l"(__cvta_generic_to_global(src)) : "memory");
}
#define CP_COMMIT() asm volatile("cp.async.commit_group;" ::: "memory")
#define CP_WAIT(n)  asm volatile("cp.async.wait_group %0;" :: "n"(n) : "memory")

__device__ __forceinline__ void ldsm4(uint32_t& r0, uint32_t& r1,
                                      uint32_t& r2, uint32_t& r3, uint32_t a) {
    asm volatile("ldmatrix.sync.aligned.m8n8.x4.shared.b16 {%0,%1,%2,%3}, [%4];"
                 : "=r"(r0), "=r"(r1), "=r"(r2), "=r"(r3) : "r"(a));
}
__device__ __forceinline__ void ldsm4t(uint32_t& r0, uint32_t& r1,
                                       uint32_t& r2, uint32_t& r3, uint32_t a) {
    asm volatile("ldmatrix.sync.aligned.m8n8.x4.trans.shared.b16 {%0,%1,%2,%3}, [%4];"
                 : "=r"(r0), "=r"(r1), "=r"(r2), "=r"(r3) : "r"(a));
}
__device__ __forceinline__ void mma16816(float* c,
        uint32_t a0, uint32_t a1, uint32_t a2, uint32_t a3,
        uint32_t b0, uint32_t b1) {
    asm volatile("mma.sync.aligned.m16n8k16.row.col.f32.bf16.bf16.f32 "
        "{%0,%1,%2,%3},{%4,%5,%6,%7},{%8,%9},{%0,%1,%2,%3};"
        : "+f"(c[0]), "+f"(c[1]), "+f"(c[2]), "+f"(c[3])
        : "r"(a0), "r"(a1), "r"(a2), "r"(a3), "r"(b0), "r"(b1));
}

__device__ __forceinline__ void split1(float v, __nv_bfloat16& h, __nv_bfloat16& l) {
    h = __float2bfloat16(v);
    l = __float2bfloat16(v - __bfloat162float(h));
}

union BP4 { unsigned long long u; __nv_bfloat16 h[4]; };

// ---------------- router + x-split fused (1st kernel) ------------------------
__global__ void router_k(const float* __restrict__ x,
                         const float* __restrict__ rw,
                         const float* __restrict__ rb) {
    int t = blockIdx.x;
    if (t == 0 && threadIdx.x < EE) g_count[threadIdx.x] = 0;

    {
        const float4* xr4 = (const float4*)(x + (size_t)t * DD);
        __nv_bfloat162* ph = (__nv_bfloat162*)(d_xh + (size_t)t * DD);
        __nv_bfloat162* pl = (__nv_bfloat162*)(d_xl + (size_t)t * DD);
#pragma unroll
        for (int i = 0; i < 2; i++) {
            int j = threadIdx.x + 128*i;
            float4 v = xr4[j];
            __nv_bfloat16 h0,l0,h1,l1,h2,l2,h3,l3;
            split1(v.x,h0,l0); split1(v.y,h1,l1);
            split1(v.z,h2,l2); split1(v.w,h3,l3);
            ph[j*2]   = __nv_bfloat162(h0,h1);  ph[j*2+1] = __nv_bfloat162(h2,h3);
            pl[j*2]   = __nv_bfloat162(l0,l1);  pl[j*2+1] = __nv_bfloat162(l2,l3);
        }
    }

    const float* xr = x + (size_t)t * DD;
    float acc[EE];
#pragma unroll
    for (int e = 0; e < EE; e++) acc[e] = 0.f;
    for (int d = threadIdx.x; d < DD; d += 128) {
        float xv = xr[d];
        const float4* r = (const float4*)(rw + (size_t)d * EE);
        float4 r0 = r[0], r1 = r[1];
        acc[0] += xv*r0.x; acc[1] += xv*r0.y; acc[2] += xv*r0.z; acc[3] += xv*r0.w;
        acc[4] += xv*r1.x; acc[5] += xv*r1.y; acc[6] += xv*r1.z; acc[7] += xv*r1.w;
    }
    __shared__ float sm[EE][128];
#pragma unroll
    for (int e = 0; e < EE; e++) sm[e][threadIdx.x] = acc[e];
    __syncthreads();
    for (int s = 64; s > 0; s >>= 1) {
        if (threadIdx.x < s)
#pragma unroll
            for (int e = 0; e < EE; e++) sm[e][threadIdx.x] += sm[e][threadIdx.x + s];
        __syncthreads();
    }
    if (threadIdx.x < EE)
        g_logits[(size_t)t*EE + threadIdx.x] = sm[threadIdx.x][0] + rb[threadIdx.x];
}

__global__ void norm_k() {
    int b = blockIdx.x >> 3, e = blockIdx.x & 7;
    float s = 0.f;
    for (int i = threadIdx.x; i < SS; i += 256) {
        float v = g_logits[((size_t)(b*SS + i))*EE + e];
        s += v*v;
    }
    __shared__ float sm[256];
    sm[threadIdx.x] = s; __syncthreads();
    for (int st = 128; st > 0; st >>= 1) {
        if (threadIdx.x < st) sm[threadIdx.x] += sm[threadIdx.x + st];
        __syncthreads();
    }
    if (threadIdx.x == 0) g_nrm[blockIdx.x] = fmaxf(sqrtf(sm[0]), 1e-12f);
}

__global__ void route_k() {
    int t = blockIdx.x*blockDim.x + threadIdx.x;
    if (t >= TT) return;
    int b = t / SS;
    float l[EE]; float m = -1e30f;
#pragma unroll
    for (int e = 0; e < EE; e++) {
        l[e] = g_logits[(size_t)t*EE + e] / g_nrm[b*EE + e];
        m = fmaxf(m, l[e]);
    }
    float sum = 0.f;
#pragma unroll
    for (int e = 0; e < EE; e++) { l[e] = expf(l[e]-m); sum += l[e]; }
    float inv = 1.f/sum;
#pragma unroll
    for (int e = 0; e < EE; e++) { l[e] *= inv; g_probs[(size_t)t*EE + e] = l[e]; }
    int i0 = 0;
#pragma unroll
    for (int e = 1; e < EE; e++) if (l[e] > l[i0]) i0 = e;
    int i1 = -1;
#pragma unroll
    for (int e = 0; e < EE; e++) {
        if (e == i0) continue;
        if (i1 < 0 || l[e] > l[i1]) i1 = e;
    }
    int s0 = atomicAdd(&g_count[i0], 1);
    g_tok[i0*TT + s0] = t; g_wt[i0*TT + s0] = l[i0];
    int s1 = atomicAdd(&g_count[i1], 1);
    g_tok[i1*TT + s1] = t; g_wt[i1*TT + s1] = l[i1];
}

__global__ void aux_k(float* __restrict__ out_aux) {
    float acc = 0.f;
    for (int i = threadIdx.x; i < SS*EE; i += 256) {
        int s = i >> 3, e = i & 7;
        float a = 0.5f*(g_probs[(size_t)s*EE + e] + g_probs[(size_t)(SS+s)*EE + e]);
        float d = 0.125f - a;
        acc += d*d;
    }
    __shared__ float sm[256];
    sm[threadIdx.x] = acc; __syncthreads();
    for (int st = 128; st > 0; st >>= 1) {
        if (threadIdx.x < st) sm[threadIdx.x] += sm[threadIdx.x + st];
        __syncthreads();
    }
    if (threadIdx.x == 0) out_aux[0] = sm[0];
}

// ---------------- GEMM1 (HMMA, term-major chains, 2 CTAs/SM) -----------------
#define G1_AB(p)  ((p)*16384)
#define G1_BB(p)  (32768 + (p)*16384)
#define G1_ST(q)  (65536 + (q)*16384)
#define G1_SMEM   98816
#define G1_NS     (DD/32)

__global__ __launch_bounds__(256, 2)
void gemm1_k(const float* __restrict__ w1, const float* __restrict__ w3) {
    extern __shared__ char smem[];
    int e = blockIdx.z;
    int cnt = g_count[e];
    int row0 = blockIdx.y * 128;
    if (row0 >= cnt) return;
    int col0 = blockIdx.x * 64;

    int tid = threadIdx.x, wid = tid >> 5, lane = tid & 31;
    uint32_t sb = smem_u32(smem);
    int* stok = (int*)(smem + 98304);

    if (tid < 128) stok[tid] = g_tok[e*TT + min(row0 + tid, cnt-1)];
    __syncthreads();

    int warpM = (wid & 1) * 64;
    int warpN = (wid >> 1) * 16;
    int fr  = (lane & 7) + ((lane >> 3) & 1) * 8;
    int fkb = (lane >> 4) * 16;

    auto cpA = [&](int s) {
        int kk = s*32;
        uint32_t base = sb + G1_AB(s & 1);
#pragma unroll
        for (int i = 0; i < 4; i++) {
            int g = tid + 256*i;
            int buf = g >> 9, idx = g & 511;
            int row = idx >> 2, c = idx & 3;
            const __nv_bfloat16* src =
                (buf ? d_xl : d_xh) + (size_t)stok[row]*DD + kk + c*8;
            cp16(base + buf*8192 + SW64(row*64 + c*16), src);
        }
    };
    auto cpB32 = [&](int s) {
        int kk = s*32;
        uint32_t base = sb + G1_ST(s & 1);
#pragma unroll
        for (int i = 0; i < 4; i++) {
            int g = tid + 256*i;
            int mat = g >> 9, idx = g & 511;
            int krow = idx >> 4, nch = idx & 15;
            const float* wp = mat ? w3 : w1;
            cp16(base + mat*8192 + krow*256 + nch*16,
                 wp + ((size_t)(e*DD + kk + krow))*HH + col0 + nch*4);
        }
    };
    auto convB = [&](int j) {
        char* src = smem + G1_ST(j & 1);
        char* dst = smem + G1_BB(j & 1);
#pragma unroll
        for (int i = 0; i < 4; i++) {
            int g = tid + 256*i;
            int mat = g >> 9, idx = g & 511;
            int krow = idx >> 4, nch = idx & 15;
            float4 v = *(float4*)(src + mat*8192 + krow*256 + nch*16);
            BP4 ph, pl;
            split1(v.x, ph.h[0], pl.h[0]);
            split1(v.y, ph.h[1], pl.h[1]);
            split1(v.z, ph.h[2], pl.h[2]);
            split1(v.w, ph.h[3], pl.h[3]);
            uint32_t off = SW128(krow*128 + nch*8);
            *(unsigned long long*)(dst + mat*8192 + off)        = ph.u;
            *(unsigned long long*)(dst + mat*8192 + 4096 + off) = pl.u;
        }
    };

    float c1[4][2][4], c3[4][2][4];
#pragma unroll
    for (int i = 0; i < 4; i++)
#pragma unroll
        for (int j = 0; j < 2; j++)
#pragma unroll
            for (int r = 0; r < 4; r++) { c1[i][j][r] = 0.f; c3[i][j][r] = 0.f; }

    cpA(0);   CP_COMMIT();
    cpB32(0); CP_COMMIT();
    cpB32(1); CP_COMMIT();
    CP_WAIT(1);
    convB(0);
    __syncthreads();

    for (int s = 0; s < G1_NS; s++) {
        int p = s & 1;
        if (s + 1 < G1_NS) cpA(s + 1);
        CP_COMMIT();
        if (s + 2 < G1_NS) cpB32(s + 2);
        CP_COMMIT();

        uint32_t ab = sb + G1_AB(p), bb = sb + G1_BB(p);
#pragma unroll
        for (int k16 = 0; k16 < 2; k16++) {
            uint32_t offB = SW128((k16*16 + fr)*128 + warpN*2 + fkb);
            uint32_t b1h[4], b1l[4], b3h[4], b3l[4];
            ldsm4t(b1h[0], b1h[1], b1h[2], b1h[3], bb + offB);
            ldsm4t(b1l[0], b1l[1], b1l[2], b1l[3], bb + 4096 + offB);
            ldsm4t(b3h[0], b3h[1], b3h[2], b3h[3], bb + 8192 + offB);
            ldsm4t(b3l[0], b3l[1], b3l[2], b3l[3], bb + 12288 + offB);
#pragma unroll
            for (int mt = 0; mt < 4; mt++) {
                uint32_t offA = SW64((warpM + mt*16 + fr)*64 + k16*32 + fkb);
                uint32_t ah[4], al[4];
                ldsm4(ah[0], ah[1], ah[2], ah[3], ab + offA);
                ldsm4(al[0], al[1], al[2], al[3], ab + 8192 + offA);
                // term-major ordering: each accumulator chain touched at gap 4
                // t0: Ah * Bh
                mma16816(c1[mt][0], ah[0],ah[1],ah[2],ah[3], b1h[0], b1h[1]);
                mma16816(c3[mt][0], ah[0],ah[1],ah[2],ah[3], b3h[0], b3h[1]);
                mma16816(c1[mt][1], ah[0],ah[1],ah[2],ah[3], b1h[2], b1h[3]);
                mma16816(c3[mt][1], ah[0],ah[1],ah[2],ah[3], b3h[2], b3h[3]);
                // t1: Al * Bh
                mma16816(c1[mt][0], al[0],al[1],al[2],al[3], b1h[0], b1h[1]);
                mma16816(c3[mt][0], al[0],al[1],al[2],al[3], b3h[0], b3h[1]);
                mma16816(c1[mt][1], al[0],al[1],al[2],al[3], b1h[2], b1h[3]);
                mma16816(c3[mt][1], al[0],al[1],al[2],al[3], b3h[2], b3h[3]);
                // t2: Ah * Bl
                mma16816(c1[mt][0], ah[0],ah[1],ah[2],ah[3], b1l[0], b1l[1]);
                mma16816(c3[mt][0], ah[0],ah[1],ah[2],ah[3], b3l[0], b3l[1]);
                mma16816(c1[mt][1], ah[0],ah[1],ah[2],ah[3], b1l[2], b1l[3]);
                mma16816(c3[mt][1], ah[0],ah[1],ah[2],ah[3], b3l[2], b3l[3]);
            }
        }

        if (s + 1 < G1_NS) {
            CP_WAIT(2);
            convB(s + 1);
            CP_WAIT(1);
            __syncthreads();
        }
    }

    // epilogue
#pragma unroll
    for (int mt = 0; mt < 4; mt++) {
#pragma unroll
        for (int half = 0; half < 2; half++) {
            int rg = row0 + warpM + mt*16 + (lane >> 2) + half*8;
            if (rg < cnt) {
                size_t rowi = (size_t)(e*TT + rg);
                size_t cb = col0 + warpN + (lane & 3)*2;
#pragma unroll
                for (int nt = 0; nt < 2; nt++) {
                    float s0 = c1[mt][nt][half*2],   g0 = c3[mt][nt][half*2];
                    float s1 = c1[mt][nt][half*2+1], g1 = c3[mt][nt][half*2+1];
                    float v0 = __sinf(s0)*g0, v1 = __sinf(s1)*g1;
                    __nv_bfloat16 h0,l0,h1,l1;
                    split1(v0,h0,l0); split1(v1,h1,l1);
                    *(__nv_bfloat162*)(d_h2 + (rowi*2)*HH   + cb + nt*8) = __nv_bfloat162(h0,h1);
                    *(__nv_bfloat162*)(d_h2 + (rowi*2+1)*HH + cb + nt*8) = __nv_bfloat162(l0,l1);
                }
            }
        }
    }
}

// ---------------- GEMM2 (HMMA, N=128, term-major chains, 2 CTAs/SM) ----------
#define G2_AB(p)  ((p)*16384)
#define G2_BB(p)  (32768 + (p)*16384)
#define G2_ST(q)  (65536 + (q)*16384)
#define G2_SMEM   99328
#define G2_NS     (HH/32)

__global__ __launch_bounds__(256, 2)
void gemm2_k(const float* __restrict__ w2, float* __restrict__ out) {
    extern __shared__ char smem[];
    int e = blockIdx.z;
    int cnt = g_count[e];
    int row0 = blockIdx.y * 128;
    if (row0 >= cnt) return;
    int col0 = blockIdx.x * 128;

    int tid = threadIdx.x, wid = tid >> 5, lane = tid & 31;
    uint32_t sb = smem_u32(smem);
    int*   stok = (int*)(smem + 98304);
    float* swt  = (float*)(smem + 98304 + 512);

    if (tid < 128) {
        int r = min(row0 + tid, cnt-1);
        stok[tid] = g_tok[e*TT + r];
        swt[tid]  = g_wt[e*TT + r];
    }
    __syncthreads();

    int warpM = (wid & 1) * 64;
    int warpN = (wid >> 1) * 32;
    int nhalf = warpN >> 6;
    int nloc  = warpN & 63;
    int fr  = (lane & 7) + ((lane >> 3) & 1) * 8;
    int fkb = (lane >> 4) * 16;
    size_t arow0 = (size_t)(e*TT + row0);

    auto cpA = [&](int s) {
        int kk = s*32;
        uint32_t base = sb + G2_AB(s & 1);
#pragma unroll
        for (int i = 0; i < 4; i++) {
            int g = tid + 256*i;
            int buf = g >> 9, idx = g & 511;
            int row = idx >> 2, c = idx & 3;
            const __nv_bfloat16* src =
                d_h2 + ((arow0 + row)*2 + buf)*HH + kk + c*8;
            cp16(base + buf*8192 + SW64(row*64 + c*16), src);
        }
    };
    auto cpB32 = [&](int s) {
        int kk = s*32;
        uint32_t base = sb + G2_ST(s & 1);
#pragma unroll
        for (int i = 0; i < 4; i++) {
            int g = tid + 256*i;
            int krow = g >> 5, nch = g & 31;
            cp16(base + krow*512 + nch*16,
                 w2 + ((size_t)(e*HH + kk + krow))*DD + col0 + nch*4);
        }
    };
    auto convB = [&](int j) {
        char* src = smem + G2_ST(j & 1);
        char* dst = smem + G2_BB(j & 1);
#pragma unroll
        for (int i = 0; i < 4; i++) {
            int g = tid + 256*i;
            int krow = g >> 5, nch = g & 31;
            float4 v = *(float4*)(src + krow*512 + nch*16);
            BP4 ph, pl;
            split1(v.x, ph.h[0], pl.h[0]);
            split1(v.y, ph.h[1], pl.h[1]);
            split1(v.z, ph.h[2], pl.h[2]);
            split1(v.w, ph.h[3], pl.h[3]);
            int half = nch >> 4, colc = nch & 15;
            uint32_t off = SW128(krow*128 + colc*8);
            *(unsigned long long*)(dst + half*8192 + off)        = ph.u;
            *(unsigned long long*)(dst + half*8192 + 4096 + off) = pl.u;
        }
    };

    float cc[4][4][4];
#pragma unroll
    for (int i = 0; i < 4; i++)
#pragma unroll
        for (int j = 0; j < 4; j++)
#pragma unroll
            for (int r = 0; r < 4; r++) cc[i][j][r] = 0.f;

    cpA(0);   CP_COMMIT();
    cpB32(0); CP_COMMIT();
    cpB32(1); CP_COMMIT();
    CP_WAIT(1);
    convB(0);
    __syncthreads();

    for (int s = 0; s < G2_NS; s++) {
        int p = s & 1;
        if (s + 1 < G2_NS) cpA(s + 1);
        CP_COMMIT();
        if (s + 2 < G2_NS) cpB32(s + 2);
        CP_COMMIT();

        uint32_t ab = sb + G2_AB(p);
        uint32_t bbh = sb + G2_BB(p) + nhalf*8192;
#pragma unroll
        for (int k16 = 0; k16 < 2; k16++) {
            uint32_t offB0 = SW128((k16*16 + fr)*128 + nloc*2 + fkb);
            uint32_t offB1 = SW128((k16*16 + fr)*128 + (nloc+16)*2 + fkb);
            uint32_t bhA[4], bhB[4], blA[4], blB[4];
            ldsm4t(bhA[0], bhA[1], bhA[2], bhA[3], bbh + offB0);
            ldsm4t(bhB[0], bhB[1], bhB[2], bhB[3], bbh + offB1);
            ldsm4t(blA[0], blA[1], blA[2], blA[3], bbh + 4096 + offB0);
            ldsm4t(blB[0], blB[1], blB[2], blB[3], bbh + 4096 + offB1);
#pragma unroll
            for (int mt = 0; mt < 4; mt++) {
                uint32_t offA = SW64((warpM + mt*16 + fr)*64 + k16*32 + fkb);
                uint32_t ah[4], al[4];
                ldsm4(ah[0], ah[1], ah[2], ah[3], ab + offA);
                ldsm4(al[0], al[1], al[2], al[3], ab + 8192 + offA);
                // term-major ordering: chains at gap 4
                // t0: Ah * Bh
                mma16816(cc[mt][0], ah[0],ah[1],ah[2],ah[3], bhA[0], bhA[1]);
                mma16816(cc[mt][1], ah[0],ah[1],ah[2],ah[3], bhA[2], bhA[3]);
                mma16816(cc[mt][2], ah[0],ah[1],ah[2],ah[3], bhB[0], bhB[1]);
                mma16816(cc[mt][3], ah[0],ah[1],ah[2],ah[3], bhB[2], bhB[3]);
                // t1: Al * Bh
                mma16816(cc[mt][0], al[0],al[1],al[2],al[3], bhA[0], bhA[1]);
                mma16816(cc[mt][1], al[0],al[1],al[2],al[3], bhA[2], bhA[3]);
                mma16816(cc[mt][2], al[0],al[1],al[2],al[3], bhB[0], bhB[1]);
                mma16816(cc[mt][3], al[0],al[1],al[2],al[3], bhB[2], bhB[3]);
                // t2: Ah * Bl
                mma16816(cc[mt][0], ah[0],ah[1],ah[2],ah[3], blA[0], blA[1]);
                mma16816(cc[mt][1], ah[0],ah[1],ah[2],ah[3], blA[2], blA[3]);
                mma16816(cc[mt][2], ah[0],ah[1],ah[2],ah[3], blB[0], blB[1]);
                mma16816(cc[mt][3], ah[0],ah[1],ah[2],ah[3], blB[2], blB[3]);
            }
        }

        if (s + 1 < G2_NS) {
            CP_WAIT(2);
            convB(s + 1);
            CP_WAIT(1);
            __syncthreads();
        }
    }

    // epilogue: weighted atomic scatter
#pragma unroll
    for (int mt = 0; mt < 4; mt++) {
#pragma unroll
        for (int half = 0; half < 2; half++) {
            int ml = warpM + mt*16 + (lane >> 2) + half*8;
            if (row0 + ml < cnt) {
                int   tok = stok[ml];
                float wt  = swt[ml];
                float* op = out + (size_t)tok*DD + col0 + warpN + (lane & 3)*2;
#pragma unroll
                for (int nt = 0; nt < 4; nt++) {
                    atomicAdd(op + nt*8 + 0, wt * cc[mt][nt][half*2]);
                    atomicAdd(op + nt*8 + 1, wt * cc[mt][nt][half*2+1]);
                }
            }
        }
    }
}

// ---------------- launch -----------------------------------------------------
extern "C" void kernel_launch(void* const* d_in, const int* in_sizes, int n_in,
                              void* d_out, int out_size) {
    const float* x  = (const float*)d_in[0];
    const float* w1 = (const float*)d_in[1];
    const float* w2 = (const float*)d_in[2];
    const float* w3 = (const float*)d_in[3];
    const float* rw = (const float*)d_in[4];
    const float* rb = (const float*)d_in[5];
    float* out = (float*)d_out;

    cudaFuncSetAttribute(gemm1_k, cudaFuncAttributeMaxDynamicSharedMemorySize, G1_SMEM);
    cudaFuncSetAttribute(gemm2_k, cudaFuncAttributeMaxDynamicSharedMemorySize, G2_SMEM);

    cudaMemsetAsync(d_out, 0, (size_t)out_size * sizeof(float));

    router_k<<<TT, 128>>>(x, rw, rb);                       // kernel 1 (+split+init)
    norm_k<<<BB*EE, 256>>>();                               // kernel 2
    route_k<<<TT/256, 256>>>();                             // kernel 3
    gemm1_k<<<dim3(HH/64, TT/128, EE), 256, G1_SMEM>>>(w1, w3);   // kernel 4 (ncu)
    gemm2_k<<<dim3(DD/128, TT/128, EE), 256, G2_SMEM>>>(w2, out); // kernel 5
    if (out_size > TT*DD) aux_k<<<1, 256>>>(out + (size_t)TT*DD); // kernel 6
}